// round 2
// baseline (speedup 1.0000x reference)
#include <cuda_runtime.h>

#define XD 38
#define YD 24
#define ZD 24
#define RV (XD*YD*ZD)          // 21888
#define BB 16
#define CC 64
#define NN 16384
#define TOTVOX (BB*RV)         // 350208  (= 342 * 1024, = 5472 * 64)
#define NPTS   (BB*NN)         // 262144
#define SCAN_BLOCKS (TOTVOX/1024)   // 342
#define GATHER_BLOCKS (TOTVOX/64)   // 5472
#define GROUPS_PER_BATCH (RV/64)    // 342

// scratch (__device__ globals; no allocations allowed)
__device__ __align__(16) int   g_cnt [TOTVOX];     // per-voxel point count
__device__ __align__(16) int   g_off [TOTVOX];     // local-exclusive prefix (within scan block)
__device__ __align__(16) int   g_bsumIn[SCAN_BLOCKS];
__device__ __align__(16) int   g_bsum  [SCAN_BLOCKS];  // exclusive scan of block totals
__device__ __align__(16) int   g_flat[NPTS];       // voxel id per point (-1 invalid)
__device__ __align__(16) int   g_rank[NPTS];       // arrival rank within voxel
__device__ __align__(16) float g_pfeat[(size_t)NPTS * CC];  // sorted point-major features (67MB)

__device__ __forceinline__ int voff(int v) { return g_off[v] + g_bsum[v >> 10]; }

__global__ void zero_cnt_k() {
    int i = blockIdx.x * blockDim.x + threadIdx.x;     // 87552 threads
    reinterpret_cast<int4*>(g_cnt)[i] = make_int4(0, 0, 0, 0);
}

__global__ void index_k(const float* __restrict__ coords) {
    int i = blockIdx.x * blockDim.x + threadIdx.x;
    if (i >= NPTS) return;
    float cx = coords[3*i + 0];
    float cy = coords[3*i + 1];
    float cz = coords[3*i + 2];
    int ix = (int)floorf(cx / 0.3f) + 19;
    int iy = (int)floorf(cy / 0.3f) + 12;
    int iz = (int)floorf(cz / 0.2f) + 12;
    bool valid = (ix >= 0) & (ix < XD) & (iy >= 0) & (iy < YD) & (iz >= 0) & (iz < ZD);
    int flat = -1, rank = 0;
    if (valid) {
        flat = ix * (YD*ZD) + iy * ZD + iz;
        int b = i / NN;
        rank = atomicAdd(&g_cnt[b*RV + flat], 1);
    }
    g_flat[i] = flat;
    g_rank[i] = rank;
}

// per-1024-element exclusive scan; block totals to g_bsumIn. 256 thr x 4 elems.
__global__ void scan_a_k() {
    __shared__ int wsum[8];
    int base = blockIdx.x * 1024 + threadIdx.x * 4;
    int4 v = *reinterpret_cast<const int4*>(&g_cnt[base]);
    int s = v.x + v.y + v.z + v.w;
    int lane = threadIdx.x & 31, wid = threadIdx.x >> 5;
    int sc = s;
    #pragma unroll
    for (int d = 1; d < 32; d <<= 1) {
        int n = __shfl_up_sync(0xFFFFFFFFu, sc, d);
        if (lane >= d) sc += n;
    }
    if (lane == 31) wsum[wid] = sc;
    __syncthreads();
    if (threadIdx.x == 0) {
        int run = 0;
        #pragma unroll
        for (int j = 0; j < 8; j++) { int t = wsum[j]; wsum[j] = run; run += t; }
        g_bsumIn[blockIdx.x] = run;
    }
    __syncthreads();
    int pre = (sc - s) + wsum[wid];    // exclusive prefix of this thread's 4 elems
    int4 o;
    o.x = pre;
    o.y = pre + v.x;
    o.z = o.y + v.y;
    o.w = o.z + v.z;
    *reinterpret_cast<int4*>(&g_off[base]) = o;
}

// single block: exclusive scan of 342 block totals
__global__ void scan_b_k() {
    __shared__ int sm[512];
    int t = threadIdx.x;
    int val = (t < SCAN_BLOCKS) ? g_bsumIn[t] : 0;
    sm[t] = val;
    __syncthreads();
    #pragma unroll
    for (int d = 1; d < 512; d <<= 1) {
        int x = (t >= d) ? sm[t - d] : 0;
        __syncthreads();
        sm[t] += x;
        __syncthreads();
    }
    if (t < SCAN_BLOCKS) g_bsum[t] = sm[t] - val;
}

// features [B,C,N] -> g_pfeat[sortedSlot][C]; grid (NN/32, BB), 256 thr
__global__ void permute_k(const float* __restrict__ feat) {
    __shared__ float sm[64][33];
    int b  = blockIdx.y;
    int p0 = blockIdx.x * 32;
    int t  = threadIdx.x;
    int j  = t & 31;
    int rb = t >> 5;                  // 0..7
    const float* fb = feat + (size_t)b * CC * NN + p0 + j;
    #pragma unroll
    for (int k = 0; k < 8; k++) {
        int row = rb + k * 8;
        sm[row][j] = fb[(size_t)row * NN];
    }
    __syncthreads();
    int jp = t >> 3;                  // point within tile 0..31
    int q  = t & 7;                   // channel octet 0..7
    int i  = b * NN + p0 + jp;
    int flat = g_flat[i];
    if (flat >= 0) {
        int v = b * RV + flat;
        size_t slot = (size_t)(voff(v) + g_rank[i]);
        float* dst = g_pfeat + slot * CC + q * 8;
        int c0 = q * 8;
        float4 a = make_float4(sm[c0+0][jp], sm[c0+1][jp], sm[c0+2][jp], sm[c0+3][jp]);
        float4 d = make_float4(sm[c0+4][jp], sm[c0+5][jp], sm[c0+6][jp], sm[c0+7][jp]);
        *reinterpret_cast<float4*>(dst)     = a;
        *reinterpret_cast<float4*>(dst + 4) = d;
    }
}

// block = 64 consecutive voxels of one batch; 512 thr = 16 warps, warp -> 4 voxels
__global__ void gather_k(float* __restrict__ out) {
    __shared__ float sm[64 * 65];     // [channel][voxel], pitch 65
    int t = threadIdx.x;
    int lane = t & 31, w = t >> 5;
    int gvbase = blockIdx.x * 64;
    const float2* pf2 = reinterpret_cast<const float2*>(g_pfeat);

    #pragma unroll
    for (int lv = 0; lv < 4; lv++) {
        int vox = w * 4 + lv;                 // 0..63
        int gv  = gvbase + vox;
        int cnt = g_cnt[gv];
        int start = voff(gv);
        float ax = 0.f, ay = 0.f;
        for (int s = start; s < start + cnt; s++) {
            float2 u = pf2[(size_t)s * 32 + lane];
            ax += u.x; ay += u.y;
        }
        float inv = 1.f / (float)max(cnt, 1);
        sm[(2*lane + 0) * 65 + vox] = ax * inv;
        sm[(2*lane + 1) * 65 + vox] = ay * inv;
    }
    __syncthreads();

    int b  = blockIdx.x / GROUPS_PER_BATCH;
    int vb = (blockIdx.x % GROUPS_PER_BATCH) * 64;
    int c  = t >> 3;                          // 0..63
    int q  = t & 7;                           // 0..7 -> 8 voxels each
    float* ob = out + ((size_t)(b * CC + c)) * RV + vb + q * 8;
    float* sp = &sm[c * 65 + q * 8];
    *reinterpret_cast<float4*>(ob)     = make_float4(sp[0], sp[1], sp[2], sp[3]);
    *reinterpret_cast<float4*>(ob + 4) = make_float4(sp[4], sp[5], sp[6], sp[7]);
}

extern "C" void kernel_launch(void* const* d_in, const int* in_sizes, int n_in,
                              void* d_out, int out_size) {
    const float* feat   = (const float*)d_in[0];   // [B, C, N]
    const float* coords = (const float*)d_in[1];   // [B, N, 3]
    float* out = (float*)d_out;                    // [B, C, X, Y, Z]

    zero_cnt_k<<<TOTVOX / 4 / 256, 256>>>();                 // 342 blocks
    index_k<<<(NPTS + 255) / 256, 256>>>(coords);            // 1024 blocks
    scan_a_k<<<SCAN_BLOCKS, 256>>>();                        // 342 blocks
    scan_b_k<<<1, 512>>>();
    permute_k<<<dim3(NN / 32, BB), 256>>>(feat);             // 8192 blocks
    gather_k<<<GATHER_BLOCKS, 512>>>(out);                   // 5472 blocks
}